// round 8
// baseline (speedup 1.0000x reference)
#include <cuda_runtime.h>
#include <cuda_bf16.h>
#include <cstdint>

// qpNet: z = max(-(x @ W^T + b), -1/EPS), EPS=1e-3  =>  z = max(-h, -1000)
// x: [B,5] f32, W: [5,5] f32, b: [5] f32, out: [B,5] f32. B = 4194304.
//
// R8: warp-granular bulk-TMA pipelines, occupancy-tuned.
// Each warp: 2560B chunk (128 rows), in[2] + out[1] smem (7680B), 2 mbarriers.
// 128-thread CTAs (4 warps) * 7 CTAs/SM = 28 warp-pipelines per SM.
// No __syncthreads anywhere; all waits are warp-local.

#define NEG_CLAMP    (-1000.0f)   // -1/EPS
#define CHUNK_FLOATS 640          // 128 rows * 5
#define CHUNK_BYTES  2560u
#define WARP_SMEM    7680         // in[2] + out[1]
#define NWARPS       4
#define MBAR_OFF     (NWARPS * WARP_SMEM)          // 30720
#define SMEM_TOTAL   (MBAR_OFF + NWARPS * 16)      // 30784

extern __shared__ char smem_raw[];

__global__ void qp_kernel(
    const float* __restrict__ x,
    const float* __restrict__ W,
    const float* __restrict__ b,
    float* __restrict__ out,
    int nchunks)
{
    const int tid  = threadIdx.x;
    const int wid  = tid >> 5;
    const int lane = tid & 31;

    char* wbase = smem_raw + wid * WARP_SMEM;
    const unsigned in_s = (unsigned)__cvta_generic_to_shared(wbase);
    const unsigned mb0  = (unsigned)__cvta_generic_to_shared(smem_raw + MBAR_OFF + wid * 16);

    if (lane == 0) {
        asm volatile("mbarrier.init.shared.b64 [%0], %1;" :: "r"(mb0),     "r"(1u));
        asm volatile("mbarrier.init.shared.b64 [%0], %1;" :: "r"(mb0 + 8), "r"(1u));
    }
    __syncwarp();   // warp-private barriers

    const long long wstride = (long long)gridDim.x * NWARPS;
    const long long g0 = (long long)blockIdx.x * NWARPS + wid;

    // ---- prologue: prefetch chunks for iterations 0 and 1 ----
    if (lane == 0) {
        if (g0 < nchunks) {
            asm volatile("mbarrier.arrive.expect_tx.shared.b64 _, [%0], %1;"
                         :: "r"(mb0), "r"(CHUNK_BYTES) : "memory");
            asm volatile("cp.async.bulk.shared::cta.global.mbarrier::complete_tx::bytes "
                         "[%0], [%1], %2, [%3];"
                         :: "r"(in_s),
                            "l"((unsigned long long)(uintptr_t)(x + g0 * CHUNK_FLOATS)),
                            "r"(CHUNK_BYTES), "r"(mb0) : "memory");
        }
        if (g0 + wstride < nchunks) {
            asm volatile("mbarrier.arrive.expect_tx.shared.b64 _, [%0], %1;"
                         :: "r"(mb0 + 8), "r"(CHUNK_BYTES) : "memory");
            asm volatile("cp.async.bulk.shared::cta.global.mbarrier::complete_tx::bytes "
                         "[%0], [%1], %2, [%3];"
                         :: "r"(in_s + CHUNK_BYTES),
                            "l"((unsigned long long)(uintptr_t)(x + (g0 + wstride) * CHUNK_FLOATS)),
                            "r"(CHUNK_BYTES), "r"(mb0 + 8) : "memory");
        }
    }

    // ---- W [5,5] + b [5] while first loads are in flight ----
    float w[5][5], bb[5];
    {
        const float4* W4 = reinterpret_cast<const float4*>(W);
        float4 a0 = __ldg(W4 + 0);
        float4 a1 = __ldg(W4 + 1);
        float4 a2 = __ldg(W4 + 2);
        float4 a3 = __ldg(W4 + 3);
        float4 a4 = __ldg(W4 + 4);
        float4 a5 = __ldg(W4 + 5);
        float  a6 = __ldg(W + 24);
        w[0][0]=a0.x; w[0][1]=a0.y; w[0][2]=a0.z; w[0][3]=a0.w; w[0][4]=a1.x;
        w[1][0]=a1.y; w[1][1]=a1.z; w[1][2]=a1.w; w[1][3]=a2.x; w[1][4]=a2.y;
        w[2][0]=a2.z; w[2][1]=a2.w; w[2][2]=a3.x; w[2][3]=a3.y; w[2][4]=a3.z;
        w[3][0]=a3.w; w[3][1]=a4.x; w[3][2]=a4.y; w[3][3]=a4.z; w[3][4]=a4.w;
        w[4][0]=a5.x; w[4][1]=a5.y; w[4][2]=a5.z; w[4][3]=a5.w; w[4][4]=a6;
        const float4* b4 = reinterpret_cast<const float4*>(b);
        float4 bv = __ldg(b4);
        bb[0]=bv.x; bb[1]=bv.y; bb[2]=bv.z; bb[3]=bv.w; bb[4]=__ldg(b + 4);
    }

    float4* __restrict__ outbuf = reinterpret_cast<float4*>(wbase + 2 * CHUNK_BYTES);
    const unsigned out_s = in_s + 2u * CHUNK_BYTES;

    for (long long g = g0, i = 0; g < nchunks; g += wstride, ++i) {
        const int      bsel = (int)(i & 1);
        const unsigned m    = mb0 + 8u * bsel;
        const int      ph   = (int)((i >> 1) & 1);
        float4* __restrict__ inbuf = reinterpret_cast<float4*>(wbase + bsel * CHUNK_BYTES);

        // ---- wait for this chunk's TMA load (warp-local) ----
        asm volatile(
            "{\n\t"
            ".reg .pred P;\n\t"
            "WAIT_%=:\n\t"
            "mbarrier.try_wait.parity.acquire.cta.shared::cta.b64 P, [%0], %1, 0x989680;\n\t"
            "@P bra DONE_%=;\n\t"
            "bra WAIT_%=;\n\t"
            "DONE_%=:\n\t"
            "}"
            :: "r"(m), "r"(ph) : "memory");

        // ---- read own 4 rows: 5x LDS.128, conflict-free (80B stride) ----
        float4 v[5];
#pragma unroll
        for (int k = 0; k < 5; k++)
            v[k] = inbuf[5 * lane + k];

        // All lanes done reading -> refill this in-buffer with chunk i+2.
        __syncwarp();
        const long long gpre = g + 2 * wstride;
        if (lane == 0 && gpre < nchunks) {
            asm volatile("mbarrier.arrive.expect_tx.shared.b64 _, [%0], %1;"
                         :: "r"(m), "r"(CHUNK_BYTES) : "memory");
            asm volatile("cp.async.bulk.shared::cta.global.mbarrier::complete_tx::bytes "
                         "[%0], [%1], %2, [%3];"
                         :: "r"(in_s + (unsigned)bsel * CHUNK_BYTES),
                            "l"((unsigned long long)(uintptr_t)(x + gpre * CHUNK_FLOATS)),
                            "r"(CHUNK_BYTES), "r"(m) : "memory");
        }

        float xr[4][5];
        xr[0][0]=v[0].x; xr[0][1]=v[0].y; xr[0][2]=v[0].z; xr[0][3]=v[0].w; xr[0][4]=v[1].x;
        xr[1][0]=v[1].y; xr[1][1]=v[1].z; xr[1][2]=v[1].w; xr[1][3]=v[2].x; xr[1][4]=v[2].y;
        xr[2][0]=v[2].z; xr[2][1]=v[2].w; xr[2][2]=v[3].x; xr[2][3]=v[3].y; xr[2][4]=v[3].z;
        xr[3][0]=v[3].w; xr[3][1]=v[4].x; xr[3][2]=v[4].y; xr[3][3]=v[4].z; xr[3][4]=v[4].w;

        float zr[4][5];
#pragma unroll
        for (int r = 0; r < 4; r++) {
#pragma unroll
            for (int j = 0; j < 5; j++) {
                float h = bb[j];
#pragma unroll
                for (int k = 0; k < 5; k++)
                    h = fmaf(xr[r][k], w[j][k], h);
                zr[r][j] = fmaxf(-h, NEG_CLAMP);
            }
        }

        // Single out-buffer: previous store (committed last iter) must have
        // READ the smem before we overwrite. read-done is engine-local/fast.
        if (lane == 0)
            asm volatile("cp.async.bulk.wait_group.read 0;" ::: "memory");
        __syncwarp();

        outbuf[5 * lane + 0] = make_float4(zr[0][0], zr[0][1], zr[0][2], zr[0][3]);
        outbuf[5 * lane + 1] = make_float4(zr[0][4], zr[1][0], zr[1][1], zr[1][2]);
        outbuf[5 * lane + 2] = make_float4(zr[1][3], zr[1][4], zr[2][0], zr[2][1]);
        outbuf[5 * lane + 3] = make_float4(zr[2][2], zr[2][3], zr[2][4], zr[3][0]);
        outbuf[5 * lane + 4] = make_float4(zr[3][1], zr[3][2], zr[3][3], zr[3][4]);

        __syncwarp();
        if (lane == 0) {
            asm volatile("fence.proxy.async.shared::cta;" ::: "memory");
            asm volatile("cp.async.bulk.global.shared::cta.bulk_group [%0], [%1], %2;"
                         :: "l"((unsigned long long)(uintptr_t)(out + g * CHUNK_FLOATS)),
                            "r"(out_s), "r"(CHUNK_BYTES) : "memory");
            asm volatile("cp.async.bulk.commit_group;" ::: "memory");
        }
    }

    // Don't exit while a bulk store may still read this CTA's smem.
    if (lane == 0)
        asm volatile("cp.async.bulk.wait_group.read 0;" ::: "memory");
}

extern "C" void kernel_launch(void* const* d_in, const int* in_sizes, int n_in,
                              void* d_out, int out_size)
{
    const float* x = (const float*)d_in[0];   // [B,5]
    const float* W = (const float*)d_in[1];   // [5,5]
    const float* b = (const float*)d_in[2];   // [5]
    float* out = (float*)d_out;               // [B,5]

    const long long B = in_sizes[0] / 5;      // 4194304
    const int nchunks = (int)(B / 128);       // 32768 chunks of 2560 B, exact

    const int threads = 128;                  // 4 warps/CTA
    const int blocks  = 152 * 7;              // 7 CTAs/SM -> 28 warps/SM
    const int smem    = SMEM_TOTAL;           // 30784 B dynamic

    cudaFuncSetAttribute(qp_kernel, cudaFuncAttributeMaxDynamicSharedMemorySize, smem);
    qp_kernel<<<blocks, threads, smem>>>(x, W, b, out, nchunks);
}

// round 9
// speedup vs baseline: 1.0176x; 1.0176x over previous
#include <cuda_runtime.h>
#include <cuda_bf16.h>
#include <cstdint>

// qpNet: z = max(-(x @ W^T + b), -1/EPS), EPS=1e-3  =>  z = max(-h, -1000)
// x: [B,5] f32, W: [5,5] f32, b: [5] f32, out: [B,5] f32. B = 4194304.
//
// R9: non-persistent (low wall-tail) + warp-decoupled stores.
//   - 4096 CTAs x 256 thr; one 20 KB bulk-TMA load per CTA (single mbarrier,
//     all threads wait it -> no __syncthreads in hot path).
//   - each warp computes its contiguous 2560 B slice (4 rows/thread via
//     conflict-free 5x LDS.128 / STS.128) and issues its own 2560 B bulk
//     store -- no block-wide rendezvous, fast warps store early.

#define NEG_CLAMP    (-1000.0f)   // -1/EPS
#define TILE_FLOATS  5120         // 1024 rows * 5
#define TILE_BYTES   20480u
#define CHUNK_FLOATS 640          // per-warp: 128 rows * 5
#define CHUNK_BYTES  2560u

__global__ __launch_bounds__(256) void qp_kernel(
    const float* __restrict__ x,
    const float* __restrict__ W,
    const float* __restrict__ b,
    float* __restrict__ out)
{
    __shared__ alignas(128) float4 inbuf[1280];    // 20 KB
    __shared__ alignas(128) float4 outbuf[1280];   // 20 KB
    __shared__ alignas(8)   unsigned long long mbar;

    const int tid  = threadIdx.x;
    const int wid  = tid >> 5;
    const int lane = tid & 31;

    const unsigned mb   = (unsigned)__cvta_generic_to_shared(&mbar);
    const unsigned in_s = (unsigned)__cvta_generic_to_shared(inbuf);
    const unsigned out_s= (unsigned)__cvta_generic_to_shared(outbuf);

    const long long base_f = (long long)blockIdx.x * TILE_FLOATS;

    // ---- init barrier + issue one 20 KB bulk load ----
    if (tid == 0)
        asm volatile("mbarrier.init.shared.b64 [%0], %1;" :: "r"(mb), "r"(1u));
    __syncthreads();
    if (tid == 0) {
        asm volatile("mbarrier.arrive.expect_tx.shared.b64 _, [%0], %1;"
                     :: "r"(mb), "r"(TILE_BYTES) : "memory");
        asm volatile("cp.async.bulk.shared::cta.global.mbarrier::complete_tx::bytes "
                     "[%0], [%1], %2, [%3];"
                     :: "r"(in_s),
                        "l"((unsigned long long)(uintptr_t)(x + base_f)),
                        "r"(TILE_BYTES), "r"(mb) : "memory");
    }

    // ---- W [5,5] + b [5] while TMA is in flight ----
    float w[5][5], bb[5];
    {
        const float4* W4 = reinterpret_cast<const float4*>(W);
        float4 a0 = __ldg(W4 + 0);
        float4 a1 = __ldg(W4 + 1);
        float4 a2 = __ldg(W4 + 2);
        float4 a3 = __ldg(W4 + 3);
        float4 a4 = __ldg(W4 + 4);
        float4 a5 = __ldg(W4 + 5);
        float  a6 = __ldg(W + 24);
        w[0][0]=a0.x; w[0][1]=a0.y; w[0][2]=a0.z; w[0][3]=a0.w; w[0][4]=a1.x;
        w[1][0]=a1.y; w[1][1]=a1.z; w[1][2]=a1.w; w[1][3]=a2.x; w[1][4]=a2.y;
        w[2][0]=a2.z; w[2][1]=a2.w; w[2][2]=a3.x; w[2][3]=a3.y; w[2][4]=a3.z;
        w[3][0]=a3.w; w[3][1]=a4.x; w[3][2]=a4.y; w[3][3]=a4.z; w[3][4]=a4.w;
        w[4][0]=a5.x; w[4][1]=a5.y; w[4][2]=a5.z; w[4][3]=a5.w; w[4][4]=a6;
        const float4* b4 = reinterpret_cast<const float4*>(b);
        float4 bv = __ldg(b4);
        bb[0]=bv.x; bb[1]=bv.y; bb[2]=bv.z; bb[3]=bv.w; bb[4]=__ldg(b + 4);
    }

    // ---- all threads wait on the load barrier (acquire: LDS follows) ----
    asm volatile(
        "{\n\t"
        ".reg .pred P;\n\t"
        "WAIT_%=:\n\t"
        "mbarrier.try_wait.parity.acquire.cta.shared::cta.b64 P, [%0], 0, 0x989680;\n\t"
        "@P bra DONE_%=;\n\t"
        "bra WAIT_%=;\n\t"
        "DONE_%=:\n\t"
        "}"
        :: "r"(mb) : "memory");

    // ---- each thread: own 4 rows via 5x LDS.128 (conflict-free, 80B stride) ----
    float4 v[5];
#pragma unroll
    for (int k = 0; k < 5; k++)
        v[k] = inbuf[5 * tid + k];

    float xr[4][5];
    xr[0][0]=v[0].x; xr[0][1]=v[0].y; xr[0][2]=v[0].z; xr[0][3]=v[0].w; xr[0][4]=v[1].x;
    xr[1][0]=v[1].y; xr[1][1]=v[1].z; xr[1][2]=v[1].w; xr[1][3]=v[2].x; xr[1][4]=v[2].y;
    xr[2][0]=v[2].z; xr[2][1]=v[2].w; xr[2][2]=v[3].x; xr[2][3]=v[3].y; xr[2][4]=v[3].z;
    xr[3][0]=v[3].w; xr[3][1]=v[4].x; xr[3][2]=v[4].y; xr[3][3]=v[4].z; xr[3][4]=v[4].w;

    float zr[4][5];
#pragma unroll
    for (int r = 0; r < 4; r++) {
#pragma unroll
        for (int j = 0; j < 5; j++) {
            float h = bb[j];
#pragma unroll
            for (int k = 0; k < 5; k++)
                h = fmaf(xr[r][k], w[j][k], h);
            zr[r][j] = fmaxf(-h, NEG_CLAMP);
        }
    }

    // ---- write z to own out slots (warp-local region) ----
    outbuf[5 * tid + 0] = make_float4(zr[0][0], zr[0][1], zr[0][2], zr[0][3]);
    outbuf[5 * tid + 1] = make_float4(zr[0][4], zr[1][0], zr[1][1], zr[1][2]);
    outbuf[5 * tid + 2] = make_float4(zr[1][3], zr[1][4], zr[2][0], zr[2][1]);
    outbuf[5 * tid + 3] = make_float4(zr[2][2], zr[2][3], zr[2][4], zr[3][0]);
    outbuf[5 * tid + 4] = make_float4(zr[3][1], zr[3][2], zr[3][3], zr[3][4]);

    // ---- per-warp bulk store of this warp's 2560 B slice ----
    __syncwarp();
    if (lane == 0) {
        asm volatile("fence.proxy.async.shared::cta;" ::: "memory");
        asm volatile("cp.async.bulk.global.shared::cta.bulk_group [%0], [%1], %2;"
                     :: "l"((unsigned long long)(uintptr_t)
                            (out + base_f + (long long)wid * CHUNK_FLOATS)),
                        "r"(out_s + (unsigned)wid * CHUNK_BYTES),
                        "r"(CHUNK_BYTES) : "memory");
        asm volatile("cp.async.bulk.commit_group;" ::: "memory");
        // CTA may not exit while the store still reads smem.
        asm volatile("cp.async.bulk.wait_group.read 0;" ::: "memory");
    }
}

extern "C" void kernel_launch(void* const* d_in, const int* in_sizes, int n_in,
                              void* d_out, int out_size)
{
    const float* x = (const float*)d_in[0];   // [B,5]
    const float* W = (const float*)d_in[1];   // [5,5]
    const float* b = (const float*)d_in[2];   // [5]
    float* out = (float*)d_out;               // [B,5]

    const long long B = in_sizes[0] / 5;      // 4194304
    const int threads = 256;
    const int blocks = (int)(B / 1024);       // 4096, exact cover

    qp_kernel<<<blocks, threads>>>(x, W, b, out);
}

// round 10
// speedup vs baseline: 1.0790x; 1.0604x over previous
#include <cuda_runtime.h>
#include <cuda_bf16.h>
#include <cstdint>

// qpNet: z = max(-(x @ W^T + b), -1/EPS), EPS=1e-3  =>  z = max(-h, -1000)
// x: [B,5] f32, W: [5,5] f32, b: [5] f32, out: [B,5] f32. B = 4194304.
//
// R10: non-persistent, single in-place smem buffer, fine-grained CTAs.
//   - 8192 CTAs x 128 thr (4 warps); tile = 512 rows = 10240 B smem.
//   - one bulk-TMA load per CTA; all threads wait the mbarrier (no
//     __syncthreads in hot path).
//   - each thread: 4 rows via 5x LDS.128 (80 B stride, conflict-free),
//     compute, write z back IN PLACE to its own slots.
//   - each warp bulk-stores its own 2560 B slice as soon as it's done.
//   - 16 CTAs/SM (warp-limited) -> 16 overlapping phases per SM.

#define NEG_CLAMP    (-1000.0f)   // -1/EPS
#define TILE_FLOATS  2560         // 512 rows * 5
#define TILE_BYTES   10240u
#define CHUNK_FLOATS 640          // per-warp: 128 rows * 5
#define CHUNK_BYTES  2560u

__global__ __launch_bounds__(128) void qp_kernel(
    const float* __restrict__ x,
    const float* __restrict__ W,
    const float* __restrict__ b,
    float* __restrict__ out)
{
    __shared__ alignas(128) float4 buf[640];           // 10 KB, in-place
    __shared__ alignas(8)   unsigned long long mbar;

    const int tid  = threadIdx.x;
    const int wid  = tid >> 5;
    const int lane = tid & 31;

    const unsigned mb  = (unsigned)__cvta_generic_to_shared(&mbar);
    const unsigned sb  = (unsigned)__cvta_generic_to_shared(buf);

    const long long base_f = (long long)blockIdx.x * TILE_FLOATS;

    // ---- init barrier + issue one 10 KB bulk load ----
    if (tid == 0)
        asm volatile("mbarrier.init.shared.b64 [%0], %1;" :: "r"(mb), "r"(1u));
    __syncthreads();
    if (tid == 0) {
        asm volatile("mbarrier.arrive.expect_tx.shared.b64 _, [%0], %1;"
                     :: "r"(mb), "r"(TILE_BYTES) : "memory");
        asm volatile("cp.async.bulk.shared::cta.global.mbarrier::complete_tx::bytes "
                     "[%0], [%1], %2, [%3];"
                     :: "r"(sb),
                        "l"((unsigned long long)(uintptr_t)(x + base_f)),
                        "r"(TILE_BYTES), "r"(mb) : "memory");
    }

    // ---- W [5,5] + b [5] while TMA is in flight ----
    float w[5][5], bb[5];
    {
        const float4* W4 = reinterpret_cast<const float4*>(W);
        float4 a0 = __ldg(W4 + 0);
        float4 a1 = __ldg(W4 + 1);
        float4 a2 = __ldg(W4 + 2);
        float4 a3 = __ldg(W4 + 3);
        float4 a4 = __ldg(W4 + 4);
        float4 a5 = __ldg(W4 + 5);
        float  a6 = __ldg(W + 24);
        w[0][0]=a0.x; w[0][1]=a0.y; w[0][2]=a0.z; w[0][3]=a0.w; w[0][4]=a1.x;
        w[1][0]=a1.y; w[1][1]=a1.z; w[1][2]=a1.w; w[1][3]=a2.x; w[1][4]=a2.y;
        w[2][0]=a2.z; w[2][1]=a2.w; w[2][2]=a3.x; w[2][3]=a3.y; w[2][4]=a3.z;
        w[3][0]=a3.w; w[3][1]=a4.x; w[3][2]=a4.y; w[3][3]=a4.z; w[3][4]=a4.w;
        w[4][0]=a5.x; w[4][1]=a5.y; w[4][2]=a5.z; w[4][3]=a5.w; w[4][4]=a6;
        const float4* b4 = reinterpret_cast<const float4*>(b);
        float4 bv = __ldg(b4);
        bb[0]=bv.x; bb[1]=bv.y; bb[2]=bv.z; bb[3]=bv.w; bb[4]=__ldg(b + 4);
    }

    // ---- all threads wait on the load barrier (acquire: LDS follows) ----
    asm volatile(
        "{\n\t"
        ".reg .pred P;\n\t"
        "WAIT_%=:\n\t"
        "mbarrier.try_wait.parity.acquire.cta.shared::cta.b64 P, [%0], 0, 0x989680;\n\t"
        "@P bra DONE_%=;\n\t"
        "bra WAIT_%=;\n\t"
        "DONE_%=:\n\t"
        "}"
        :: "r"(mb) : "memory");

    // ---- each thread: own 4 rows via 5x LDS.128 (conflict-free) ----
    float4 v[5];
#pragma unroll
    for (int k = 0; k < 5; k++)
        v[k] = buf[5 * tid + k];

    float xr[4][5];
    xr[0][0]=v[0].x; xr[0][1]=v[0].y; xr[0][2]=v[0].z; xr[0][3]=v[0].w; xr[0][4]=v[1].x;
    xr[1][0]=v[1].y; xr[1][1]=v[1].z; xr[1][2]=v[1].w; xr[1][3]=v[2].x; xr[1][4]=v[2].y;
    xr[2][0]=v[2].z; xr[2][1]=v[2].w; xr[2][2]=v[3].x; xr[2][3]=v[3].y; xr[2][4]=v[3].z;
    xr[3][0]=v[3].w; xr[3][1]=v[4].x; xr[3][2]=v[4].y; xr[3][3]=v[4].z; xr[3][4]=v[4].w;

    float zr[4][5];
#pragma unroll
    for (int r = 0; r < 4; r++) {
#pragma unroll
        for (int j = 0; j < 5; j++) {
            float h = bb[j];
#pragma unroll
            for (int k = 0; k < 5; k++)
                h = fmaf(xr[r][k], w[j][k], h);
            zr[r][j] = fmaxf(-h, NEG_CLAMP);
        }
    }

    // ---- write z back IN PLACE to own slots (within-thread hazard only) ----
    buf[5 * tid + 0] = make_float4(zr[0][0], zr[0][1], zr[0][2], zr[0][3]);
    buf[5 * tid + 1] = make_float4(zr[0][4], zr[1][0], zr[1][1], zr[1][2]);
    buf[5 * tid + 2] = make_float4(zr[1][3], zr[1][4], zr[2][0], zr[2][1]);
    buf[5 * tid + 3] = make_float4(zr[2][2], zr[2][3], zr[2][4], zr[3][0]);
    buf[5 * tid + 4] = make_float4(zr[3][1], zr[3][2], zr[3][3], zr[3][4]);

    // ---- per-warp bulk store of this warp's 2560 B slice ----
    __syncwarp();
    if (lane == 0) {
        asm volatile("fence.proxy.async.shared::cta;" ::: "memory");
        asm volatile("cp.async.bulk.global.shared::cta.bulk_group [%0], [%1], %2;"
                     :: "l"((unsigned long long)(uintptr_t)
                            (out + base_f + (long long)wid * CHUNK_FLOATS)),
                        "r"(sb + (unsigned)wid * CHUNK_BYTES),
                        "r"(CHUNK_BYTES) : "memory");
        asm volatile("cp.async.bulk.commit_group;" ::: "memory");
        // CTA must not exit while its store still reads smem.
        asm volatile("cp.async.bulk.wait_group.read 0;" ::: "memory");
    }
}

extern "C" void kernel_launch(void* const* d_in, const int* in_sizes, int n_in,
                              void* d_out, int out_size)
{
    const float* x = (const float*)d_in[0];   // [B,5]
    const float* W = (const float*)d_in[1];   // [5,5]
    const float* b = (const float*)d_in[2];   // [5]
    float* out = (float*)d_out;               // [B,5]

    const long long B = in_sizes[0] / 5;      // 4194304
    const int threads = 128;
    const int blocks = (int)(B / 512);        // 8192, exact cover

    qp_kernel<<<blocks, threads>>>(x, W, b, out);
}